// round 5
// baseline (speedup 1.0000x reference)
#include <cuda_runtime.h>
#include <math.h>

// Shapes: feature (8,128,80,256) fp32; ln_weight/ln_bias (128)
// B2=4, H=80, W=256, C=128
// Outputs (concatenated fp32):
//   disparity (4,1,80,256)   @ 0          (81920)
//   conf      (4,1,80,256)   @ 81920      (81920)
//   occ       (4,1,80,256)   @ 163840     (81920)
//   cv        (4,80,256,256) @ 245760     (20971520)
//   cv_down   (4,40,128,128) @ 21217280   (2621440)

#define NEG_INF __int_as_float(0xff800000)

// 84 MB scratch: first holds xn, then reused as cvT.
__device__ float g_scratch[20971520];

// ---------------------------------------------------------------------------
// ~1-ulp fp32 exp/log from FFMA polynomials; deterministic, fast-math-immune.
// ---------------------------------------------------------------------------
__device__ __forceinline__ float exp_acc(float x) {
    if (x < -87.0f) return 0.f;
    float kf = rintf(x * 1.44269504088896341f);
    float f  = fmaf(kf, -6.93145752e-1f, x);
    f        = fmaf(kf, -1.42860677e-6f, f);
    float p = 1.98412698e-4f;
    p = fmaf(p, f, 1.38888889e-3f);
    p = fmaf(p, f, 8.33333333e-3f);
    p = fmaf(p, f, 4.16666667e-2f);
    p = fmaf(p, f, 1.66666667e-1f);
    p = fmaf(p, f, 5.0e-1f);
    p = fmaf(p, f, 1.0f);
    p = fmaf(p, f, 1.0f);
    int ki = (int)kf;
    return p * __int_as_float((ki + 127) << 23);
}

__device__ __forceinline__ float log_acc(float x) {
    int ix = __float_as_int(x);
    int e  = (ix >> 23) - 127;
    float mf = __int_as_float((ix & 0x7FFFFF) | 0x3F800000);
    if (mf > 1.41421356f) { mf *= 0.5f; e += 1; }
    float r  = (mf - 1.0f) / (mf + 1.0f);
    float r2 = r * r;
    float p = 0.10376f;
    p = fmaf(p, r2, 0.11119022f);
    p = fmaf(p, r2, 0.14285414f);
    p = fmaf(p, r2, 0.20000029f);
    p = fmaf(p, r2, 0.33333333f);
    p = fmaf(p, r2, 1.0f);
    p = 2.0f * r * p;
    float ef = (float)e;
    return fmaf(ef, 6.93145752e-1f, p) + ef * 1.42860677e-6f;
}

// ---------------------------------------------------------------------------
// Kernel 1: LayerNorm emulating XLA-CPU bit order:
//  mean: serial ascending fp32 sum, *1/128 (exact)
//  var:  serial ascending fp32 sum of rn(x-mu)^2, *1/128
//  rs:   1/sqrt(var+eps), each op correctly-rounded fp32
//  out:  separate rn mul/mul/add (no FMA contraction)
// feature[b,c,h,i] -> xn[((b*80+h)*256+i)*128+c]
// ---------------------------------------------------------------------------
__global__ void __launch_bounds__(256) ln_kernel(const float* __restrict__ f,
                                                 const float* __restrict__ lw,
                                                 const float* __restrict__ lb,
                                                 float* __restrict__ xn) {
    __shared__ float tile[128][65];
    __shared__ float mu[64], rs[64];
    __shared__ float wv[128], bv[128];
    int i0  = blockIdx.x * 64;
    int h   = blockIdx.y;
    int b   = blockIdx.z;
    int tid = threadIdx.x;
    if (tid < 128) { wv[tid] = lw[tid]; bv[tid] = lb[tid]; }

    const float* fp = f + ((b * 128) * 80 + h) * 256 + i0;
    for (int idx = tid; idx < 128 * 64; idx += 256) {
        int c = idx >> 6, ii = idx & 63;
        tile[c][ii] = fp[c * (80 * 256) + ii];
    }
    __syncthreads();

    if (tid < 64) {
        float s = 0.f;
        for (int c = 0; c < 128; ++c) s = __fadd_rn(s, tile[c][tid]);
        float muf = __fmul_rn(s, 0.0078125f);           // exact /128
        float vs = 0.f;
        for (int c = 0; c < 128; ++c) {
            float d = __fsub_rn(tile[c][tid], muf);
            vs = __fadd_rn(vs, __fmul_rn(d, d));
        }
        float varf = __fmul_rn(vs, 0.0078125f);
        mu[tid] = muf;
        rs[tid] = __fdiv_rn(1.0f, __fsqrt_rn(__fadd_rn(varf, 1e-5f)));
    }
    __syncthreads();

    float* op = xn + ((b * 80 + h) * 256 + i0) * 128;
    for (int idx = tid; idx < 8192; idx += 256) {
        int ii = idx >> 7, c = idx & 127;
        float xm = __fsub_rn(tile[c][ii], mu[ii]);
        float t  = __fmul_rn(__fmul_rn(xm, rs[ii]), wv[c]);
        op[ii * 128 + c] = __fadd_rn(t, bv[c]);
    }
}

// ---------------------------------------------------------------------------
// Kernel 2: cv = f0 @ f1^T per (b,h). Serial ascending-k FMA chain per output
// (bit-matches Eigen gebp / cublas SIMT accumulation).
// ---------------------------------------------------------------------------
__global__ void __launch_bounds__(256) gemm_kernel(const float* __restrict__ xn,
                                                   float* __restrict__ cv) {
    __shared__ float As[32][128];
    __shared__ float Bs[32][128];
    int bh = blockIdx.y;
    int ti = blockIdx.x >> 1, tj = blockIdx.x & 1;
    const float* Ag = xn + bh * 32768 + ti * 16384;
    const float* Bg = xn + (bh + 320) * 32768 + tj * 16384;
    int tid = threadIdx.x;
    int m0 = (tid >> 4) << 3;
    int n0 = (tid & 15) << 3;

    float acc[8][8];
    #pragma unroll
    for (int r = 0; r < 8; ++r)
        #pragma unroll
        for (int c = 0; c < 8; ++c) acc[r][c] = 0.f;

    for (int k0 = 0; k0 < 128; k0 += 32) {
        __syncthreads();
        #pragma unroll
        for (int q = tid; q < 1024; q += 256) {
            int m = q & 127, kq = q >> 7;
            float4 va = *(const float4*)(Ag + m * 128 + k0 + kq * 4);
            As[kq * 4 + 0][m] = va.x; As[kq * 4 + 1][m] = va.y;
            As[kq * 4 + 2][m] = va.z; As[kq * 4 + 3][m] = va.w;
            float4 vb = *(const float4*)(Bg + m * 128 + k0 + kq * 4);
            Bs[kq * 4 + 0][m] = vb.x; Bs[kq * 4 + 1][m] = vb.y;
            Bs[kq * 4 + 2][m] = vb.z; Bs[kq * 4 + 3][m] = vb.w;
        }
        __syncthreads();
        #pragma unroll 8
        for (int k = 0; k < 32; ++k) {
            float4 a0 = *(const float4*)&As[k][m0];
            float4 a1 = *(const float4*)&As[k][m0 + 4];
            float4 b0 = *(const float4*)&Bs[k][n0];
            float4 b1 = *(const float4*)&Bs[k][n0 + 4];
            float a[8] = {a0.x, a0.y, a0.z, a0.w, a1.x, a1.y, a1.z, a1.w};
            float bb[8] = {b0.x, b0.y, b0.z, b0.w, b1.x, b1.y, b1.z, b1.w};
            #pragma unroll
            for (int r = 0; r < 8; ++r)
                #pragma unroll
                for (int c = 0; c < 8; ++c) acc[r][c] = fmaf(a[r], bb[c], acc[r][c]);
        }
    }

    float* Cp = cv + bh * 65536 + (ti * 128 + m0) * 256 + tj * 128 + n0;
    #pragma unroll
    for (int r = 0; r < 8; ++r) {
        *(float4*)(Cp + r * 256)     = make_float4(acc[r][0], acc[r][1], acc[r][2], acc[r][3]);
        *(float4*)(Cp + r * 256 + 4) = make_float4(acc[r][4], acc[r][5], acc[r][6], acc[r][7]);
    }
}

// ---------------------------------------------------------------------------
// Kernel 3: per-(b,h) 256x256 transpose cv -> cvT
// ---------------------------------------------------------------------------
__global__ void __launch_bounds__(256) transpose_kernel(const float* __restrict__ cv,
                                                        float* __restrict__ cvT) {
    __shared__ float t[32][33];
    int bh = blockIdx.y;
    int ti = blockIdx.x >> 3, tj = blockIdx.x & 7;
    const float* src = cv + bh * 65536;
    float* dst = cvT + bh * 65536;
    int x = threadIdx.x & 31;
    int y = threadIdx.x >> 5;
    int i0 = ti * 32, j0 = tj * 32;
    #pragma unroll
    for (int r = y; r < 32; r += 8) t[r][x] = src[(i0 + r) * 256 + j0 + x];
    __syncthreads();
    #pragma unroll
    for (int r = y; r < 32; r += 8) dst[(j0 + r) * 256 + i0 + x] = t[x][r];
}

// ---------------------------------------------------------------------------
// Kernel 4: cv_down[b,hd,id,jd] = cv[b, 2hd, 2id, 2jd]
// (Same dot products over same 128 channels, same FMA order -> bitwise equal.)
// ---------------------------------------------------------------------------
__global__ void __launch_bounds__(256) cvdown_kernel(const float* __restrict__ cv,
                                                     float* __restrict__ cvd) {
    int idx = blockIdx.x * 256 + threadIdx.x;
    if (idx >= 4 * 40 * 128 * 128) return;
    int jd = idx & 127;
    int id = (idx >> 7) & 127;
    int t  = idx >> 14;
    int hd = t % 40, b = t / 40;
    cvd[idx] = cv[((b * 80 + 2 * hd) * 256 + 2 * id) * 256 + 2 * jd];
}

// ---------------------------------------------------------------------------
// Kernel 5: Sinkhorn + outputs, emulating XLA-CPU serial fp32 reductions:
//  - amax: max reduce (order-independent) via parallel butterfly
//  - sum:  exp terms computed in parallel to smem, then lane 0 replays the
//          SERIAL ascending fp32 add chain; pad element (idx 256) added last
//  - v/u:  rn(log_mu - rn(m + log(s)))
//  - final: t = rn(rn(rn(a+u)+v)+log512), p = exp(t); argmax(p) first-max;
//           occ = serial ascending sum of p; window conf/corr ascending.
// One CTA (512 thr) per (b,h); triangle-only work; one warp per row/col.
// ---------------------------------------------------------------------------
__global__ void __launch_bounds__(512) sinkhorn_kernel(const float* __restrict__ cv,
                                                       const float* __restrict__ cvT,
                                                       float* __restrict__ disp,
                                                       float* __restrict__ conf,
                                                       float* __restrict__ occ) {
    __shared__ float u[257], v[257];
    __shared__ float buf[16][256];
    int bh = blockIdx.x;
    const float* A  = cv  + bh * 65536;   // A[i*256+j]
    const float* AT = cvT + bh * 65536;   // AT[j*256+i]
    int tid = threadIdx.x, lane = tid & 31, warp = tid >> 5;
    const float LMS = -6.2383246250395075f;  // log(1/512)
    const float LMB = -0.69314718055994531f; // log(1/2)
    const float L2W =  6.2383246250395075f;  // log(512)

    for (int k = tid; k < 257; k += 512) u[k] = 0.f;
    __syncthreads();

    for (int it = 0; it < 8; ++it) {
        // ---- v-step: columns j; valid i in [j,255], pad i=256 last ----
        for (int j = warp; j < 257; j += 16) {
            float* B = buf[warp];
            float pad = u[256];
            float m = pad;
            if (j < 256) {
                const float* col = AT + j * 256;
                for (int i = j + lane; i < 256; i += 32) {
                    float t = __fadd_rn(col[i], u[i]);
                    B[i] = t;
                    m = fmaxf(m, t);
                }
            } else {
                for (int i = lane; i < 256; i += 32) {
                    float t = u[i];
                    B[i] = t;
                    m = fmaxf(m, t);
                }
            }
            #pragma unroll
            for (int off = 16; off; off >>= 1)
                m = fmaxf(m, __shfl_xor_sync(0xffffffffu, m, off));
            __syncwarp();
            {
                int lo = (j < 256) ? j : 0;
                for (int i = lo + lane; i < 256; i += 32)
                    B[i] = exp_acc(__fsub_rn(B[i], m));
            }
            __syncwarp();
            if (lane == 0) {
                float s = 0.f;
                int lo = (j < 256) ? j : 0;
                for (int i = lo; i < 256; ++i) s = __fadd_rn(s, B[i]);
                s = __fadd_rn(s, exp_acc(__fsub_rn(pad, m)));   // pad LAST
                v[j] = __fsub_rn((j < 256) ? LMS : LMB,
                                 __fadd_rn(m, log_acc(s)));
            }
            __syncwarp();
        }
        __syncthreads();
        // ---- u-step: rows i; valid j in [0,i], pad j=256 last ----
        for (int i = warp; i < 257; i += 16) {
            float* B = buf[warp];
            float pad = v[256];
            float m = pad;
            int len = (i < 256) ? (i + 1) : 256;
            if (i < 256) {
                const float* row = A + i * 256;
                for (int j = lane; j < len; j += 32) {
                    float t = __fadd_rn(row[j], v[j]);
                    B[j] = t;
                    m = fmaxf(m, t);
                }
            } else {
                for (int j = lane; j < 256; j += 32) {
                    float t = v[j];
                    B[j] = t;
                    m = fmaxf(m, t);
                }
            }
            #pragma unroll
            for (int off = 16; off; off >>= 1)
                m = fmaxf(m, __shfl_xor_sync(0xffffffffu, m, off));
            __syncwarp();
            for (int j = lane; j < len; j += 32)
                B[j] = exp_acc(__fsub_rn(B[j], m));
            __syncwarp();
            if (lane == 0) {
                float s = 0.f;
                for (int j = 0; j < len; ++j) s = __fadd_rn(s, B[j]);
                s = __fadd_rn(s, exp_acc(__fsub_rn(pad, m)));   // pad LAST
                u[i] = __fsub_rn((i < 256) ? LMS : LMB,
                                 __fadd_rn(m, log_acc(s)));
            }
            __syncwarp();
        }
        __syncthreads();
    }

    // ---- Final: p = exp(((a+u)+v)+log512); argmax/occ/conf/corr ----
    for (int i = warp; i < 256; i += 16) {
        float* B = buf[warp];
        const float* row = A + i * 256;
        float ui = u[i];
        float bm = -1.f;
        int bj = 1 << 30;
        for (int j = lane; j <= i; j += 32) {
            float t = __fadd_rn(__fadd_rn(__fadd_rn(row[j], ui), v[j]), L2W);
            float p = exp_acc(t);
            B[j] = p;
            if (p > bm || (p == bm && j < bj)) { bm = p; bj = j; }
        }
        #pragma unroll
        for (int off = 16; off; off >>= 1) {
            float bm2 = __shfl_xor_sync(0xffffffffu, bm, off);
            int   bj2 = __shfl_xor_sync(0xffffffffu, bj, off);
            if (bm2 > bm || (bm2 == bm && bj2 < bj)) { bm = bm2; bj = bj2; }
        }
        __syncwarp();
        if (lane == 0) {
            float sum = 0.f;
            for (int j = 0; j <= i; ++j) sum = __fadd_rn(sum, B[j]);  // serial occ
            float cf = 0.f, cn = 0.f;
            #pragma unroll
            for (int d = -2; d <= 2; ++d) {
                int jp = bj + d;
                if (jp >= 0 && jp <= i) {
                    float p = B[jp];
                    cf = __fadd_rn(cf, p);
                    cn = __fadd_rn(cn, __fmul_rn(p, (float)jp));
                }
            }
            float corr = __fdiv_rn(__fadd_rn(cn, 1e-4f), __fadd_rn(cf, 1e-4f));
            int o = bh * 256 + i;
            disp[o] = __fsub_rn((float)i, corr);
            conf[o] = cf;
            occ[o]  = sum;
        }
        __syncwarp();
    }
}

// ---------------------------------------------------------------------------
extern "C" void kernel_launch(void* const* d_in, const int* in_sizes, int n_in,
                              void* d_out, int out_size) {
    const float* feature = (const float*)d_in[0];
    const float* lnw     = (const float*)d_in[1];
    const float* lnb     = (const float*)d_in[2];
    float* out  = (float*)d_out;
    float* disp = out;
    float* conf = out + 81920;
    float* occ  = out + 163840;
    float* cv   = out + 245760;
    float* cvd  = out + 21217280;

    float* scratch;
    cudaGetSymbolAddress((void**)&scratch, g_scratch);

    ln_kernel<<<dim3(4, 80, 8), 256>>>(feature, lnw, lnb, scratch);
    gemm_kernel<<<dim3(4, 320), 256>>>(scratch, cv);
    transpose_kernel<<<dim3(64, 320), 256>>>(cv, scratch);
    cvdown_kernel<<<10240, 256>>>(cv, cvd);
    sinkhorn_kernel<<<320, 512>>>(cv, scratch, disp, conf, occ);
}

// round 6
// speedup vs baseline: 1.3831x; 1.3831x over previous
#include <cuda_runtime.h>
#include <math.h>

// Shapes: feature (8,128,80,256) fp32; ln_weight/ln_bias (128)
// B2=4, H=80, W=256, C=128
// Outputs (concatenated fp32):
//   disparity (4,1,80,256)   @ 0          (81920)
//   conf      (4,1,80,256)   @ 81920      (81920)
//   occ       (4,1,80,256)   @ 163840     (81920)
//   cv        (4,80,256,256) @ 245760     (20971520)
//   cv_down   (4,40,128,128) @ 21217280   (2621440)

#define NEG_INF __int_as_float(0xff800000)

// 84 MB scratch: first holds xn, then reused as cvT.
__device__ float g_scratch[20971520];

// ---------------------------------------------------------------------------
// ~1-ulp fp32 exp/log from FFMA polynomials; deterministic, fast-math-immune.
// ---------------------------------------------------------------------------
__device__ __forceinline__ float exp_acc(float x) {
    if (x < -87.0f) return 0.f;
    float kf = rintf(x * 1.44269504088896341f);
    float f  = fmaf(kf, -6.93145752e-1f, x);
    f        = fmaf(kf, -1.42860677e-6f, f);
    float p = 1.98412698e-4f;
    p = fmaf(p, f, 1.38888889e-3f);
    p = fmaf(p, f, 8.33333333e-3f);
    p = fmaf(p, f, 4.16666667e-2f);
    p = fmaf(p, f, 1.66666667e-1f);
    p = fmaf(p, f, 5.0e-1f);
    p = fmaf(p, f, 1.0f);
    p = fmaf(p, f, 1.0f);
    int ki = (int)kf;
    return p * __int_as_float((ki + 127) << 23);
}

__device__ __forceinline__ float log_acc(float x) {
    int ix = __float_as_int(x);
    int e  = (ix >> 23) - 127;
    float mf = __int_as_float((ix & 0x7FFFFF) | 0x3F800000);
    if (mf > 1.41421356f) { mf *= 0.5f; e += 1; }
    float r  = (mf - 1.0f) / (mf + 1.0f);
    float r2 = r * r;
    float p = 0.10376f;
    p = fmaf(p, r2, 0.11119022f);
    p = fmaf(p, r2, 0.14285414f);
    p = fmaf(p, r2, 0.20000029f);
    p = fmaf(p, r2, 0.33333333f);
    p = fmaf(p, r2, 1.0f);
    p = 2.0f * r * p;
    float ef = (float)e;
    return fmaf(ef, 6.93145752e-1f, p) + ef * 1.42860677e-6f;
}

// ---------------------------------------------------------------------------
// Kernel 1: LayerNorm emulating XLA-CPU bit order (serial fp32 sums).
// feature[b,c,h,i] -> xn[((b*80+h)*256+i)*128+c]
// ---------------------------------------------------------------------------
__global__ void __launch_bounds__(256) ln_kernel(const float* __restrict__ f,
                                                 const float* __restrict__ lw,
                                                 const float* __restrict__ lb,
                                                 float* __restrict__ xn) {
    __shared__ float tile[128][65];
    __shared__ float mu[64], rs[64];
    __shared__ float wv[128], bv[128];
    int i0  = blockIdx.x * 64;
    int h   = blockIdx.y;
    int b   = blockIdx.z;
    int tid = threadIdx.x;
    if (tid < 128) { wv[tid] = lw[tid]; bv[tid] = lb[tid]; }

    const float* fp = f + ((b * 128) * 80 + h) * 256 + i0;
    for (int idx = tid; idx < 128 * 64; idx += 256) {
        int c = idx >> 6, ii = idx & 63;
        tile[c][ii] = fp[c * (80 * 256) + ii];
    }
    __syncthreads();

    if (tid < 64) {
        float s = 0.f;
        for (int c = 0; c < 128; ++c) s = __fadd_rn(s, tile[c][tid]);
        float muf = __fmul_rn(s, 0.0078125f);           // exact /128
        float vs = 0.f;
        for (int c = 0; c < 128; ++c) {
            float d = __fsub_rn(tile[c][tid], muf);
            vs = __fadd_rn(vs, __fmul_rn(d, d));
        }
        float varf = __fmul_rn(vs, 0.0078125f);
        mu[tid] = muf;
        rs[tid] = __fdiv_rn(1.0f, __fsqrt_rn(__fadd_rn(varf, 1e-5f)));
    }
    __syncthreads();

    float* op = xn + ((b * 80 + h) * 256 + i0) * 128;
    for (int idx = tid; idx < 8192; idx += 256) {
        int ii = idx >> 7, c = idx & 127;
        float xm = __fsub_rn(tile[c][ii], mu[ii]);
        float t  = __fmul_rn(__fmul_rn(xm, rs[ii]), wv[c]);
        op[ii * 128 + c] = __fadd_rn(t, bv[c]);
    }
}

// ---------------------------------------------------------------------------
// Kernel 2: cv = f0 @ f1^T per (b,h). Serial ascending-k FMA chain per output.
// ---------------------------------------------------------------------------
__global__ void __launch_bounds__(256) gemm_kernel(const float* __restrict__ xn,
                                                   float* __restrict__ cv) {
    __shared__ float As[32][128];
    __shared__ float Bs[32][128];
    int bh = blockIdx.y;
    int ti = blockIdx.x >> 1, tj = blockIdx.x & 1;
    const float* Ag = xn + bh * 32768 + ti * 16384;
    const float* Bg = xn + (bh + 320) * 32768 + tj * 16384;
    int tid = threadIdx.x;
    int m0 = (tid >> 4) << 3;
    int n0 = (tid & 15) << 3;

    float acc[8][8];
    #pragma unroll
    for (int r = 0; r < 8; ++r)
        #pragma unroll
        for (int c = 0; c < 8; ++c) acc[r][c] = 0.f;

    for (int k0 = 0; k0 < 128; k0 += 32) {
        __syncthreads();
        #pragma unroll
        for (int q = tid; q < 1024; q += 256) {
            int m = q & 127, kq = q >> 7;
            float4 va = *(const float4*)(Ag + m * 128 + k0 + kq * 4);
            As[kq * 4 + 0][m] = va.x; As[kq * 4 + 1][m] = va.y;
            As[kq * 4 + 2][m] = va.z; As[kq * 4 + 3][m] = va.w;
            float4 vb = *(const float4*)(Bg + m * 128 + k0 + kq * 4);
            Bs[kq * 4 + 0][m] = vb.x; Bs[kq * 4 + 1][m] = vb.y;
            Bs[kq * 4 + 2][m] = vb.z; Bs[kq * 4 + 3][m] = vb.w;
        }
        __syncthreads();
        #pragma unroll 8
        for (int k = 0; k < 32; ++k) {
            float4 a0 = *(const float4*)&As[k][m0];
            float4 a1 = *(const float4*)&As[k][m0 + 4];
            float4 b0 = *(const float4*)&Bs[k][n0];
            float4 b1 = *(const float4*)&Bs[k][n0 + 4];
            float a[8] = {a0.x, a0.y, a0.z, a0.w, a1.x, a1.y, a1.z, a1.w};
            float bb[8] = {b0.x, b0.y, b0.z, b0.w, b1.x, b1.y, b1.z, b1.w};
            #pragma unroll
            for (int r = 0; r < 8; ++r)
                #pragma unroll
                for (int c = 0; c < 8; ++c) acc[r][c] = fmaf(a[r], bb[c], acc[r][c]);
        }
    }

    float* Cp = cv + bh * 65536 + (ti * 128 + m0) * 256 + tj * 128 + n0;
    #pragma unroll
    for (int r = 0; r < 8; ++r) {
        *(float4*)(Cp + r * 256)     = make_float4(acc[r][0], acc[r][1], acc[r][2], acc[r][3]);
        *(float4*)(Cp + r * 256 + 4) = make_float4(acc[r][4], acc[r][5], acc[r][6], acc[r][7]);
    }
}

// ---------------------------------------------------------------------------
// Kernel 3: per-(b,h) 256x256 transpose cv -> cvT
// ---------------------------------------------------------------------------
__global__ void __launch_bounds__(256) transpose_kernel(const float* __restrict__ cv,
                                                        float* __restrict__ cvT) {
    __shared__ float t[32][33];
    int bh = blockIdx.y;
    int ti = blockIdx.x >> 3, tj = blockIdx.x & 7;
    const float* src = cv + bh * 65536;
    float* dst = cvT + bh * 65536;
    int x = threadIdx.x & 31;
    int y = threadIdx.x >> 5;
    int i0 = ti * 32, j0 = tj * 32;
    #pragma unroll
    for (int r = y; r < 32; r += 8) t[r][x] = src[(i0 + r) * 256 + j0 + x];
    __syncthreads();
    #pragma unroll
    for (int r = y; r < 32; r += 8) dst[(j0 + r) * 256 + i0 + x] = t[x][r];
}

// ---------------------------------------------------------------------------
// Kernel 4: cv_down[b,hd,id,jd] = cv[b, 2hd, 2id, 2jd]
// ---------------------------------------------------------------------------
__global__ void __launch_bounds__(256) cvdown_kernel(const float* __restrict__ cv,
                                                     float* __restrict__ cvd) {
    int idx = blockIdx.x * 256 + threadIdx.x;
    if (idx >= 4 * 40 * 128 * 128) return;
    int jd = idx & 127;
    int id = (idx >> 7) & 127;
    int t  = idx >> 14;
    int hd = t % 40, b = t / 40;
    cvd[idx] = cv[((b * 80 + 2 * hd) * 256 + 2 * id) * 256 + 2 * jd];
}

// ---------------------------------------------------------------------------
// Kernel 5: Sinkhorn + outputs. Identical arithmetic order to R5 (XLA-CPU
// serial fp32 chains), but restructured for chain-level parallelism:
// per sweep, lines are processed in batches of 32:
//   Phase A (warp-parallel): each warp fills 2 lines (t=a+u, warp max,
//            in-place exp(t-m)) into smem buf rows.
//   Phase B (thread-per-line): 32 threads concurrently replay the serial
//            ascending fp32 add chain of their line (pad element last).
// ---------------------------------------------------------------------------
__global__ void __launch_bounds__(512) sinkhorn_kernel(const float* __restrict__ cv,
                                                       const float* __restrict__ cvT,
                                                       float* __restrict__ disp,
                                                       float* __restrict__ conf,
                                                       float* __restrict__ occ) {
    __shared__ float u[257], v[257];
    __shared__ float buf[32 * 257];   // 32 lines x 257 stride (bank-safe)
    __shared__ float mx[32];
    __shared__ int   bjs[32];
    int bh = blockIdx.x;
    const float* A  = cv  + bh * 65536;   // A[i*256+j]
    const float* AT = cvT + bh * 65536;   // AT[j*256+i]
    int tid = threadIdx.x, lane = tid & 31, warp = tid >> 5;
    const float LMS = -6.2383246250395075f;  // log(1/512)
    const float LMB = -0.69314718055994531f; // log(1/2)
    const float L2W =  6.2383246250395075f;  // log(512)

    for (int k = tid; k < 257; k += 512) u[k] = 0.f;
    __syncthreads();

    for (int it = 0; it < 8; ++it) {
        // ================= v-step: columns j; valid i in [j,255] =================
        for (int base = 0; base < 257; base += 32) {
            #pragma unroll
            for (int q = 0; q < 2; ++q) {
                int l = base + 2 * warp + q;
                if (l < 257) {
                    float* B = buf + (2 * warp + q) * 257;
                    float pad = u[256];
                    float m = pad;
                    if (l < 256) {
                        const float* col = AT + l * 256;
                        for (int i = l + lane; i < 256; i += 32) {
                            float t = __fadd_rn(col[i], u[i]);
                            B[i] = t;
                            m = fmaxf(m, t);
                        }
                    } else {
                        for (int i = lane; i < 256; i += 32) {
                            float t = u[i];
                            B[i] = t;
                            m = fmaxf(m, t);
                        }
                    }
                    #pragma unroll
                    for (int off = 16; off; off >>= 1)
                        m = fmaxf(m, __shfl_xor_sync(0xffffffffu, m, off));
                    __syncwarp();
                    int lo = (l < 256) ? l : 0;
                    for (int i = lo + lane; i < 256; i += 32)
                        B[i] = exp_acc(__fsub_rn(B[i], m));
                    if (lane == 0) mx[2 * warp + q] = m;
                }
            }
            __syncthreads();
            if (tid < 32) {
                int l = base + tid;
                if (l < 257) {
                    const float* B = buf + tid * 257;
                    float m = mx[tid];
                    float s = 0.f;
                    int lo = (l < 256) ? l : 0;
                    #pragma unroll 4
                    for (int i = lo; i < 256; ++i) s = __fadd_rn(s, B[i]);
                    s = __fadd_rn(s, exp_acc(__fsub_rn(u[256], m)));   // pad LAST
                    v[l] = __fsub_rn((l < 256) ? LMS : LMB,
                                     __fadd_rn(m, log_acc(s)));
                }
            }
            __syncthreads();
        }
        // ================= u-step: rows i; valid j in [0,i] =================
        for (int base = 0; base < 257; base += 32) {
            #pragma unroll
            for (int q = 0; q < 2; ++q) {
                int l = base + 2 * warp + q;
                if (l < 257) {
                    float* B = buf + (2 * warp + q) * 257;
                    float pad = v[256];
                    float m = pad;
                    int len = (l < 256) ? (l + 1) : 256;
                    if (l < 256) {
                        const float* row = A + l * 256;
                        for (int j = lane; j < len; j += 32) {
                            float t = __fadd_rn(row[j], v[j]);
                            B[j] = t;
                            m = fmaxf(m, t);
                        }
                    } else {
                        for (int j = lane; j < 256; j += 32) {
                            float t = v[j];
                            B[j] = t;
                            m = fmaxf(m, t);
                        }
                    }
                    #pragma unroll
                    for (int off = 16; off; off >>= 1)
                        m = fmaxf(m, __shfl_xor_sync(0xffffffffu, m, off));
                    __syncwarp();
                    for (int j = lane; j < len; j += 32)
                        B[j] = exp_acc(__fsub_rn(B[j], m));
                    if (lane == 0) mx[2 * warp + q] = m;
                }
            }
            __syncthreads();
            if (tid < 32) {
                int l = base + tid;
                if (l < 257) {
                    const float* B = buf + tid * 257;
                    float m = mx[tid];
                    int len = (l < 256) ? (l + 1) : 256;
                    float s = 0.f;
                    #pragma unroll 4
                    for (int j = 0; j < len; ++j) s = __fadd_rn(s, B[j]);
                    s = __fadd_rn(s, exp_acc(__fsub_rn(v[256], m)));   // pad LAST
                    u[l] = __fsub_rn((l < 256) ? LMS : LMB,
                                     __fadd_rn(m, log_acc(s)));
                }
            }
            __syncthreads();
        }
    }

    // ====== Final: p = exp(((a+u)+v)+log512); argmax/occ/conf/corr ======
    for (int base = 0; base < 256; base += 32) {
        #pragma unroll
        for (int q = 0; q < 2; ++q) {
            int i = base + 2 * warp + q;          // always < 256
            float* B = buf + (2 * warp + q) * 257;
            const float* row = A + i * 256;
            float ui = u[i];
            float bm = -1.f;
            int bj = 1 << 30;
            for (int j = lane; j <= i; j += 32) {
                float t = __fadd_rn(__fadd_rn(__fadd_rn(row[j], ui), v[j]), L2W);
                float p = exp_acc(t);
                B[j] = p;
                if (p > bm || (p == bm && j < bj)) { bm = p; bj = j; }
            }
            #pragma unroll
            for (int off = 16; off; off >>= 1) {
                float bm2 = __shfl_xor_sync(0xffffffffu, bm, off);
                int   bj2 = __shfl_xor_sync(0xffffffffu, bj, off);
                if (bm2 > bm || (bm2 == bm && bj2 < bj)) { bm = bm2; bj = bj2; }
            }
            if (lane == 0) bjs[2 * warp + q] = bj;
        }
        __syncthreads();
        if (tid < 32) {
            int i = base + tid;
            const float* B = buf + tid * 257;
            float sum = 0.f;
            #pragma unroll 4
            for (int j = 0; j <= i; ++j) sum = __fadd_rn(sum, B[j]);   // serial occ
            int bj = bjs[tid];
            float cf = 0.f, cn = 0.f;
            #pragma unroll
            for (int d = -2; d <= 2; ++d) {
                int jp = bj + d;
                if (jp >= 0 && jp <= i) {
                    float p = B[jp];
                    cf = __fadd_rn(cf, p);
                    cn = __fadd_rn(cn, __fmul_rn(p, (float)jp));
                }
            }
            float corr = __fdiv_rn(__fadd_rn(cn, 1e-4f), __fadd_rn(cf, 1e-4f));
            int o = bh * 256 + i;
            disp[o] = __fsub_rn((float)i, corr);
            conf[o] = cf;
            occ[o]  = sum;
        }
        __syncthreads();
    }
}

// ---------------------------------------------------------------------------
extern "C" void kernel_launch(void* const* d_in, const int* in_sizes, int n_in,
                              void* d_out, int out_size) {
    const float* feature = (const float*)d_in[0];
    const float* lnw     = (const float*)d_in[1];
    const float* lnb     = (const float*)d_in[2];
    float* out  = (float*)d_out;
    float* disp = out;
    float* conf = out + 81920;
    float* occ  = out + 163840;
    float* cv   = out + 245760;
    float* cvd  = out + 21217280;

    float* scratch;
    cudaGetSymbolAddress((void**)&scratch, g_scratch);

    ln_kernel<<<dim3(4, 80, 8), 256>>>(feature, lnw, lnb, scratch);
    gemm_kernel<<<dim3(4, 320), 256>>>(scratch, cv);
    transpose_kernel<<<dim3(64, 320), 256>>>(cv, scratch);
    cvdown_kernel<<<10240, 256>>>(cv, cvd);
    sinkhorn_kernel<<<320, 512>>>(cv, scratch, disp, conf, occ);
}